// round 1
// baseline (speedup 1.0000x reference)
#include <cuda_runtime.h>
#include <math.h>

#define BB 2
#define KK 4096
#define DD 192
#define H1 96
#define W1 320
#define H2 48
#define W2 160
#define H3 24
#define W3 80
#define H4 12
#define W4 40

// Scratch: projected channel-last feature maps (allocation-free __device__ globals)
__device__ float g_m1[(size_t)BB * H1 * W1 * DD];  // feat_l1 @ w_loc_w[:64]
__device__ float g_m2[(size_t)BB * H2 * W2 * DD];  // feat_l2 @ proj_l2_w
__device__ float g_m3[(size_t)BB * H3 * W3 * DD];  // feat_l3 transposed
__device__ float g_m4[(size_t)BB * H4 * W4 * DD];  // feat_l4 @ proj_l4_w

// ---------------------------------------------------------------------------
// Precompute: out[b, p, d] = sum_c feat[b, c, p] * Wm[c, d]   (channel-last)
// ---------------------------------------------------------------------------
template <int CIN, int LVL>
__global__ __launch_bounds__(DD) void proj_map_kernel(
    const float* __restrict__ feat, const float* __restrict__ Wm, int npix)
{
    constexpr int TX = 8;
    __shared__ float sf[CIN * TX];
    float* outmap = (LVL == 1) ? g_m1 : (LVL == 2) ? g_m2 : g_m4;

    const int b = blockIdx.y;
    const int p0 = blockIdx.x * TX;
    const float* fb = feat + (size_t)b * CIN * npix + p0;

    for (int i = threadIdx.x; i < CIN * TX; i += DD) {
        int c = i >> 3, p = i & 7;
        sf[i] = fb[(size_t)c * npix + p];
    }
    __syncthreads();

    const int d = threadIdx.x;
    float acc[TX];
#pragma unroll
    for (int p = 0; p < TX; p++) acc[p] = 0.f;

    for (int c = 0; c < CIN; c++) {
        float w = Wm[c * DD + d];
#pragma unroll
        for (int p = 0; p < TX; p++) acc[p] = fmaf(sf[c * TX + p], w, acc[p]);
    }

    float* ob = outmap + ((size_t)b * npix + p0) * DD + d;
#pragma unroll
    for (int p = 0; p < TX; p++) ob[p * DD] = acc[p];
}

// Channel-last transpose for l3 (no projection)
__global__ __launch_bounds__(DD) void l3_transpose_kernel(const float* __restrict__ feat)
{
    __shared__ float s[32][DD + 1];
    const int npix = H3 * W3;
    const int b = blockIdx.y;
    const int p0 = blockIdx.x * 32;

    for (int i = threadIdx.x; i < DD * 32; i += DD) {
        int d = i >> 5, p = i & 31;
        s[p][d] = feat[((size_t)b * DD + d) * npix + p0 + p];
    }
    __syncthreads();

    const int d = threadIdx.x;
#pragma unroll 4
    for (int p = 0; p < 32; p++)
        g_m3[((size_t)b * npix + p0 + p) * DD + d] = s[p][d];
}

// ---------------------------------------------------------------------------
// Bilinear sample from a channel-last map, zero padding, align_corners=True
// ---------------------------------------------------------------------------
__device__ __forceinline__ float sample_cl(const float* __restrict__ mb, int H, int W,
                                           float x, float y, int d)
{
    float x0f = floorf(x), y0f = floorf(y);
    float wx1 = x - x0f, wy1 = y - y0f;
    float wx0 = 1.f - wx1, wy0 = 1.f - wy1;
    int x0 = (int)x0f, y0 = (int)y0f;
    int x1 = x0 + 1, y1 = y0 + 1;
    bool vx0 = (unsigned)x0 < (unsigned)W;
    bool vx1 = (unsigned)x1 < (unsigned)W;

    float acc = 0.f;
    if ((unsigned)y0 < (unsigned)H) {
        const float* r = mb + (size_t)(y0 * W) * DD + d;
        if (vx0) acc = fmaf(wx0 * wy0, r[(size_t)x0 * DD], acc);
        if (vx1) acc = fmaf(wx1 * wy0, r[(size_t)x1 * DD], acc);
    }
    if ((unsigned)y1 < (unsigned)H) {
        const float* r = mb + (size_t)(y1 * W) * DD + d;
        if (vx0) acc = fmaf(wx0 * wy1, r[(size_t)x0 * DD], acc);
        if (vx1) acc = fmaf(wx1 * wy1, r[(size_t)x1 * DD], acc);
    }
    return acc;
}

// ---------------------------------------------------------------------------
// Main per-query kernel: one block per (b, k); thread = output channel d
// ---------------------------------------------------------------------------
__global__ __launch_bounds__(DD) void token_kernel(
    const float* __restrict__ feat_l1,
    const float* __restrict__ coords,
    const float* __restrict__ proj_l2_b,
    const float* __restrict__ proj_l4_b,
    const float* __restrict__ w_off_w, const float* __restrict__ w_off_b,
    const float* __restrict__ w_loc_w, const float* __restrict__ w_loc_b,
    const float* __restrict__ w_q_w,   const float* __restrict__ w_q_b,
    const float* __restrict__ e_l1, const float* __restrict__ e_l2,
    const float* __restrict__ e_l3, const float* __restrict__ e_l4,
    const float* __restrict__ rpe,
    float* __restrict__ out_tokens, float* __restrict__ out_seed)
{
    __shared__ float s_fc[64];
    __shared__ float s_pe[32];
    __shared__ float s_offx[32];
    __shared__ float s_offy[32];
    __shared__ float s_phi[512];
    __shared__ float s_w2[16 * DD];

    const int q = blockIdx.x;
    const int b = q >> 12;          // K = 4096
    const int tid = threadIdx.x;
    const float x = coords[2 * q], y = coords[2 * q + 1];
    const float TWO_PI = 6.283185307179586f;

    if (tid < 64) {
        // f_center: bilinear from channel-first feat_l1 at coords/4
        const float* fp = feat_l1 + ((size_t)b * 64 + tid) * (H1 * W1);
        float xs = x * 0.25f, ys = y * 0.25f;
        float x0f = floorf(xs), y0f = floorf(ys);
        float wx1 = xs - x0f, wy1 = ys - y0f;
        float wx0 = 1.f - wx1, wy0 = 1.f - wy1;
        int x0 = (int)x0f, y0 = (int)y0f, x1 = x0 + 1, y1 = y0 + 1;
        float acc = 0.f;
        if ((unsigned)y0 < (unsigned)H1) {
            if ((unsigned)x0 < (unsigned)W1) acc = fmaf(wx0 * wy0, fp[y0 * W1 + x0], acc);
            if ((unsigned)x1 < (unsigned)W1) acc = fmaf(wx1 * wy0, fp[y0 * W1 + x1], acc);
        }
        if ((unsigned)y1 < (unsigned)H1) {
            if ((unsigned)x0 < (unsigned)W1) acc = fmaf(wx0 * wy1, fp[y1 * W1 + x0], acc);
            if ((unsigned)x1 < (unsigned)W1) acc = fmaf(wx1 * wy1, fp[y1 * W1 + x1], acc);
        }
        s_fc[tid] = acc;
    } else if (tid < 96) {
        // pe_q: fourier_pe(coords / [W_IMG, H_IMG], 8) -> [sinx8, cosx8, siny8, cosy8]
        int j = tid - 64;
        float cn = (j < 16) ? x * (1.f / 1280.f) : y * (1.f / 384.f);
        float ang = cn * TWO_PI * (float)(1 << (j & 7));
        s_pe[j] = ((j >> 3) & 1) ? cosf(ang) : sinf(ang);
    } else if (tid < 120) {
        // FIXED_OFFSETS: 5x5 grid (dx fastest), skip center (idx 12)
        int i = tid - 96;
        int idx = (i < 12) ? i : i + 1;
        s_offx[i] = (float)(idx % 5 - 2);
        s_offy[i] = (float)(idx / 5 - 2);
    }
    // cache w_loc_w rows 64..79 (phi part of the l1 projection)
    for (int i = tid; i < 16 * DD; i += DD) s_w2[i] = w_loc_w[64 * DD + i];
    __syncthreads();

    // learned offsets: 6*tanh(f_center @ w_off_w + b), reshape (8,2)
    if (tid < 16) {
        float a = w_off_b[tid];
#pragma unroll 8
        for (int c = 0; c < 64; c++) a = fmaf(s_fc[c], w_off_w[c * 16 + tid], a);
        float v = 6.f * tanhf(a);
        if (tid & 1) s_offy[24 + (tid >> 1)] = v;
        else         s_offx[24 + (tid >> 1)] = v;
    }
    __syncthreads();

    // phi = fourier_pe(all_off, 4): per point [sinx4, cosx4, siny4, cosy4]
    for (int i = tid; i < 512; i += DD) {
        int t = i >> 4, j = i & 15;
        float c = (j < 8) ? s_offx[t] : s_offy[t];
        float ang = c * TWO_PI * (float)(1 << (j & 3));
        s_phi[i] = ((j >> 2) & 1) ? cosf(ang) : sinf(ang);
    }
    __syncthreads();

    // seed = [f_center, pe_q] @ w_q_w + w_q_b
    {
        float a = w_q_b[tid];
#pragma unroll 4
        for (int c = 0; c < 64; c++) a = fmaf(s_fc[c], w_q_w[c * DD + tid], a);
#pragma unroll 4
        for (int j = 0; j < 32; j++) a = fmaf(s_pe[j], w_q_w[(64 + j) * DD + tid], a);
        out_seed[(size_t)q * DD + tid] = a;
    }

    float* tb = out_tokens + (size_t)q * 91 * DD + tid;

    // --- l1 tokens (32): gelu(sample(m1) + phi @ W2 + b) + e_l1 ---
    {
        const float xc = x * 0.25f, yc = y * 0.25f;
        const float wlb = w_loc_b[tid], e1 = e_l1[tid];
        const float* m1b = g_m1 + (size_t)b * (H1 * W1) * DD;
        const float* w2 = s_w2 + tid;
        for (int t = 0; t < 32; t++) {
            float v = sample_cl(m1b, H1, W1, xc + s_offx[t], yc + s_offy[t], tid);
            const float* ph = s_phi + t * 16;
#pragma unroll
            for (int j = 0; j < 16; j++) v = fmaf(ph[j], w2[j * DD], v);
            v += wlb;
            float g = 0.5f * v * (1.f + erff(v * 0.7071067811865476f));
            tb[t * DD] = g + e1;
        }
    }
    // --- l2 tokens (25) ---
    {
        const float bb2 = proj_l2_b[tid] + e_l2[tid];
        const float x2 = x * 0.125f, y2 = y * 0.125f;
        const float* m2b = g_m2 + (size_t)b * (H2 * W2) * DD;
        for (int t = 0; t < 25; t++) {
            float v = sample_cl(m2b, H2, W2, x2 + (float)(t % 5 - 2), y2 + (float)(t / 5 - 2), tid);
            tb[(32 + t) * DD] = v + bb2 + rpe[t * DD + tid];
        }
    }
    // --- l3 tokens (25) ---
    {
        const float e3 = e_l3[tid];
        const float x3 = x * 0.0625f, y3 = y * 0.0625f;
        const float* m3b = g_m3 + (size_t)b * (H3 * W3) * DD;
        for (int t = 0; t < 25; t++) {
            float v = sample_cl(m3b, H3, W3, x3 + (float)(t % 5 - 2), y3 + (float)(t / 5 - 2), tid);
            tb[(57 + t) * DD] = v + e3 + rpe[t * DD + tid];
        }
    }
    // --- l4 tokens (9) ---
    {
        const float bb4 = proj_l4_b[tid] + e_l4[tid];
        const float x4 = x * 0.03125f, y4 = y * 0.03125f;
        const float* m4b = g_m4 + (size_t)b * (H4 * W4) * DD;
        for (int t = 0; t < 9; t++) {
            float v = sample_cl(m4b, H4, W4, x4 + (float)(t % 3 - 1), y4 + (float)(t / 3 - 1), tid);
            int ridx = 6 + (t / 3) * 5 + (t % 3);   // L4_RPE_IDX
            tb[(82 + t) * DD] = v + bb4 + rpe[ridx * DD + tid];
        }
    }
}

// ---------------------------------------------------------------------------
extern "C" void kernel_launch(void* const* d_in, const int* in_sizes, int n_in,
                              void* d_out, int out_size)
{
    const float* feat_l1   = (const float*)d_in[0];
    const float* feat_l2   = (const float*)d_in[1];
    const float* feat_l3   = (const float*)d_in[2];
    const float* feat_l4   = (const float*)d_in[3];
    const float* coords    = (const float*)d_in[4];
    const float* proj_l2_w = (const float*)d_in[5];
    const float* proj_l2_b = (const float*)d_in[6];
    const float* proj_l4_w = (const float*)d_in[7];
    const float* proj_l4_b = (const float*)d_in[8];
    const float* w_off_w   = (const float*)d_in[9];
    const float* w_off_b   = (const float*)d_in[10];
    const float* w_loc_w   = (const float*)d_in[11];
    const float* w_loc_b   = (const float*)d_in[12];
    const float* w_q_w     = (const float*)d_in[13];
    const float* w_q_b     = (const float*)d_in[14];
    const float* e_l1      = (const float*)d_in[15];
    const float* e_l2      = (const float*)d_in[16];
    const float* e_l3      = (const float*)d_in[17];
    const float* e_l4      = (const float*)d_in[18];
    const float* rpe       = (const float*)d_in[19];

    float* out = (float*)d_out;
    float* out_tokens = out;
    float* out_seed = out + (size_t)BB * KK * 91 * DD;

    proj_map_kernel<64, 1><<<dim3(H1 * W1 / 8, BB), DD>>>(feat_l1, w_loc_w, H1 * W1);
    proj_map_kernel<128, 2><<<dim3(H2 * W2 / 8, BB), DD>>>(feat_l2, proj_l2_w, H2 * W2);
    proj_map_kernel<384, 4><<<dim3(H4 * W4 / 8, BB), DD>>>(feat_l4, proj_l4_w, H4 * W4);
    l3_transpose_kernel<<<dim3(H3 * W3 / 32, BB), DD>>>(feat_l3);

    token_kernel<<<BB * KK, DD>>>(feat_l1, coords, proj_l2_b, proj_l4_b,
                                  w_off_w, w_off_b, w_loc_w, w_loc_b,
                                  w_q_w, w_q_b, e_l1, e_l2, e_l3, e_l4, rpe,
                                  out_tokens, out_seed);
}

// round 2
// speedup vs baseline: 1.1705x; 1.1705x over previous
#include <cuda_runtime.h>
#include <math.h>

#define BB 2
#define KK 4096
#define DD 192
#define H1 96
#define W1 320
#define H2 48
#define W2 160
#define H3 24
#define W3 80
#define H4 12
#define W4 40

// Scratch (allocation-free __device__ globals)
__device__ float g_m1[(size_t)BB * H1 * W1 * DD];  // feat_l1 @ w_loc_w[:64]
__device__ float g_c1[(size_t)BB * H1 * W1 * 64];  // feat_l1 channel-last (raw)
__device__ float g_m2[(size_t)BB * H2 * W2 * DD];  // feat_l2 @ proj_l2_w
__device__ float g_m3[(size_t)BB * H3 * W3 * DD];  // feat_l3 channel-last
__device__ float g_m4[(size_t)BB * H4 * W4 * DD];  // feat_l4 @ proj_l4_w

// Precomputed per-token constant tables
__device__ float g_phiW[24 * DD];  // phi(fixed_off) @ W2 + w_loc_b
__device__ float g_add2[25 * DD];  // proj_l2_b + e_l2 + rpe
__device__ float g_add3[25 * DD];  // e_l3 + rpe
__device__ float g_add4[9 * DD];   // proj_l4_b + e_l4 + rpe[L4_RPE_IDX]

#define TWO_PI 6.283185307179586f

// ---------------------------------------------------------------------------
// Precompute: out[b, p, d] = sum_c feat[b, c, p] * Wm[c, d]   (channel-last)
// For LVL==1 also emits the raw channel-last copy g_c1.
// ---------------------------------------------------------------------------
template <int CIN, int LVL>
__global__ __launch_bounds__(DD) void proj_map_kernel(
    const float* __restrict__ feat, const float* __restrict__ Wm, int npix)
{
    constexpr int TX = 8;
    __shared__ float sf[CIN * TX];
    float* outmap = (LVL == 1) ? g_m1 : (LVL == 2) ? g_m2 : g_m4;

    const int b = blockIdx.y;
    const int p0 = blockIdx.x * TX;
    const float* fb = feat + (size_t)b * CIN * npix + p0;

    for (int i = threadIdx.x; i < CIN * TX; i += DD) {
        int c = i >> 3, p = i & 7;
        sf[i] = fb[(size_t)c * npix + p];
    }
    __syncthreads();

    if (LVL == 1) {
        // raw channel-last copy (64 channels)
        for (int i = threadIdx.x; i < 64 * TX; i += DD) {
            int p = i >> 6, c = i & 63;
            g_c1[((size_t)b * npix + p0 + p) * 64 + c] = sf[c * TX + p];
        }
    }

    const int d = threadIdx.x;
    float acc[TX];
#pragma unroll
    for (int p = 0; p < TX; p++) acc[p] = 0.f;

    for (int c = 0; c < CIN; c++) {
        float w = Wm[c * DD + d];
#pragma unroll
        for (int p = 0; p < TX; p++) acc[p] = fmaf(sf[c * TX + p], w, acc[p]);
    }

    float* ob = outmap + ((size_t)b * npix + p0) * DD + d;
#pragma unroll
    for (int p = 0; p < TX; p++) ob[p * DD] = acc[p];
}

// Channel-last transpose for l3 (no projection)
__global__ __launch_bounds__(DD) void l3_transpose_kernel(const float* __restrict__ feat)
{
    __shared__ float s[32][DD + 1];
    const int npix = H3 * W3;
    const int b = blockIdx.y;
    const int p0 = blockIdx.x * 32;

    for (int i = threadIdx.x; i < DD * 32; i += DD) {
        int d = i >> 5, p = i & 31;
        s[p][d] = feat[((size_t)b * DD + d) * npix + p0 + p];
    }
    __syncthreads();

    const int d = threadIdx.x;
#pragma unroll 4
    for (int p = 0; p < 32; p++)
        g_m3[((size_t)b * npix + p0 + p) * DD + d] = s[p][d];
}

// ---------------------------------------------------------------------------
// Init constant tables (83 blocks x 192 threads)
// ---------------------------------------------------------------------------
__global__ __launch_bounds__(DD) void init_tables_kernel(
    const float* __restrict__ w_loc_w, const float* __restrict__ w_loc_b,
    const float* __restrict__ proj_l2_b, const float* __restrict__ e_l2,
    const float* __restrict__ e_l3,
    const float* __restrict__ proj_l4_b, const float* __restrict__ e_l4,
    const float* __restrict__ rpe)
{
    const int bid = blockIdx.x;
    const int d = threadIdx.x;
    if (bid < 24) {
        int t = bid;
        int idx = (t < 12) ? t : t + 1;
        float dx = (float)(idx % 5 - 2), dy = (float)(idx / 5 - 2);
        float a = w_loc_b[d];
#pragma unroll
        for (int j = 0; j < 16; j++) {
            float c = (j < 8) ? dx : dy;
            float ang = c * TWO_PI * (float)(1 << (j & 3));
            float v = ((j >> 2) & 1) ? cosf(ang) : sinf(ang);
            a = fmaf(v, w_loc_w[(64 + j) * DD + d], a);
        }
        g_phiW[t * DD + d] = a;
    } else if (bid < 49) {
        int t = bid - 24;
        g_add2[t * DD + d] = proj_l2_b[d] + e_l2[d] + rpe[t * DD + d];
    } else if (bid < 74) {
        int t = bid - 49;
        g_add3[t * DD + d] = e_l3[d] + rpe[t * DD + d];
    } else {
        int t = bid - 74;
        int ridx = 6 + (t / 3) * 5 + (t % 3);
        g_add4[t * DD + d] = proj_l4_b[d] + e_l4[d] + rpe[ridx * DD + d];
    }
}

// ---------------------------------------------------------------------------
// Bilinear sample from a channel-last map (arbitrary position)
// ---------------------------------------------------------------------------
__device__ __forceinline__ float sample_cl(const float* __restrict__ mb, int H, int W,
                                           float x, float y, int d)
{
    float x0f = floorf(x), y0f = floorf(y);
    float wx1 = x - x0f, wy1 = y - y0f;
    float wx0 = 1.f - wx1, wy0 = 1.f - wy1;
    int x0 = (int)x0f, y0 = (int)y0f;
    int x1 = x0 + 1, y1 = y0 + 1;
    bool vx0 = (unsigned)x0 < (unsigned)W;
    bool vx1 = (unsigned)x1 < (unsigned)W;

    float acc = 0.f;
    if ((unsigned)y0 < (unsigned)H) {
        const float* r = mb + (size_t)(y0 * W) * DD + d;
        if (vx0) acc = fmaf(wx0 * wy0, r[(size_t)x0 * DD], acc);
        if (vx1) acc = fmaf(wx1 * wy0, r[(size_t)x1 * DD], acc);
    }
    if ((unsigned)y1 < (unsigned)H) {
        const float* r = mb + (size_t)(y1 * W) * DD + d;
        if (vx0) acc = fmaf(wx0 * wy1, r[(size_t)x0 * DD], acc);
        if (vx1) acc = fmaf(wx1 * wy1, r[(size_t)x1 * DD], acc);
    }
    return acc;
}

// ---------------------------------------------------------------------------
// Patch-shared bilinear sampling for an integer-offset grid.
// R = grid radius; emits (2R+1)^2 values via emit(ty, tx, v).
// Corner patch is (2R+2) x (2R+2); interp is separable.
// ---------------------------------------------------------------------------
template <int H, int W, int R, typename F>
__device__ __forceinline__ void patch_sample(const float* __restrict__ mb,
                                             float xs, float ys, int d, F&& emit)
{
    constexpr int PC = 2 * R + 2;   // corner rows/cols
    float xf = floorf(xs), yf = floorf(ys);
    float wx1 = xs - xf, wx0 = 1.f - wx1;
    float wy1 = ys - yf, wy0 = 1.f - wy1;
    int bx0 = (int)xf - R, by0 = (int)yf - R;

    const float* md = mb + d;
    float hprev[PC - 1];

    for (int r = 0; r < PC; r++) {
        int yy = by0 + r;
        bool yok = (unsigned)yy < (unsigned)H;
        float p[PC];
#pragma unroll
        for (int c = 0; c < PC; c++) {
            int xx = bx0 + c;
            bool ok = yok && ((unsigned)xx < (unsigned)W);
            p[c] = ok ? md[(size_t)(yy * W + xx) * DD] : 0.f;
        }
        float hcur[PC - 1];
#pragma unroll
        for (int c = 0; c < PC - 1; c++) hcur[c] = fmaf(wx1, p[c + 1], wx0 * p[c]);
        if (r > 0) {
#pragma unroll
            for (int c = 0; c < PC - 1; c++)
                emit(r - 1, c, fmaf(wy1, hcur[c], wy0 * hprev[c]));
        }
#pragma unroll
        for (int c = 0; c < PC - 1; c++) hprev[c] = hcur[c];
    }
}

// ---------------------------------------------------------------------------
// Main per-query kernel: one block per (b, k); thread = output channel d
// ---------------------------------------------------------------------------
__global__ __launch_bounds__(DD) void token_kernel(
    const float* __restrict__ coords,
    const float* __restrict__ w_off_w, const float* __restrict__ w_off_b,
    const float* __restrict__ w_loc_w, const float* __restrict__ w_loc_b,
    const float* __restrict__ w_q_w,   const float* __restrict__ w_q_b,
    const float* __restrict__ e_l1,
    float* __restrict__ out_tokens, float* __restrict__ out_seed)
{
    __shared__ float s_fc[64];
    __shared__ float s_pe[32];
    __shared__ float s_lx[8];
    __shared__ float s_ly[8];
    __shared__ float s_phiL[128];
    __shared__ float s_w2[16 * DD];

    const int q = blockIdx.x;
    const int b = q >> 12;          // K = 4096
    const int tid = threadIdx.x;
    const float x = coords[2 * q], y = coords[2 * q + 1];

    if (tid < 64) {
        // f_center from channel-last raw l1 copy
        float xs = x * 0.25f, ys = y * 0.25f;
        float x0f = floorf(xs), y0f = floorf(ys);
        float wx1 = xs - x0f, wy1 = ys - y0f;
        float wx0 = 1.f - wx1, wy0 = 1.f - wy1;
        int x0 = (int)x0f, y0 = (int)y0f, x1 = x0 + 1, y1 = y0 + 1;
        bool vx0 = (unsigned)x0 < (unsigned)W1, vx1 = (unsigned)x1 < (unsigned)W1;
        const float* cb = g_c1 + (size_t)b * (H1 * W1) * 64 + tid;
        float acc = 0.f;
        if ((unsigned)y0 < (unsigned)H1) {
            if (vx0) acc = fmaf(wx0 * wy0, cb[(size_t)(y0 * W1 + x0) * 64], acc);
            if (vx1) acc = fmaf(wx1 * wy0, cb[(size_t)(y0 * W1 + x1) * 64], acc);
        }
        if ((unsigned)y1 < (unsigned)H1) {
            if (vx0) acc = fmaf(wx0 * wy1, cb[(size_t)(y1 * W1 + x0) * 64], acc);
            if (vx1) acc = fmaf(wx1 * wy1, cb[(size_t)(y1 * W1 + x1) * 64], acc);
        }
        s_fc[tid] = acc;
    } else if (tid < 96) {
        // pe_q: fourier_pe(coords / [W_IMG, H_IMG], 8)
        int j = tid - 64;
        float cn = (j < 16) ? x * (1.f / 1280.f) : y * (1.f / 384.f);
        float ang = cn * TWO_PI * (float)(1 << (j & 7));
        s_pe[j] = ((j >> 3) & 1) ? cosf(ang) : sinf(ang);
    }
    // cache w_loc_w rows 64..79 (phi part of the l1 projection)
    for (int i = tid; i < 16 * DD; i += DD) s_w2[i] = w_loc_w[64 * DD + i];
    __syncthreads();

    // learned offsets: 6*tanh(f_center @ w_off_w + b) -> (8,2)
    if (tid < 16) {
        float a = w_off_b[tid];
#pragma unroll 8
        for (int c = 0; c < 64; c++) a = fmaf(s_fc[c], w_off_w[c * 16 + tid], a);
        float v = 6.f * tanhf(a);
        if (tid & 1) s_ly[tid >> 1] = v;
        else         s_lx[tid >> 1] = v;
    }

    // seed = [f_center, pe_q] @ w_q_w + w_q_b   (independent of offsets)
    {
        float a = w_q_b[tid];
#pragma unroll 4
        for (int c = 0; c < 64; c++) a = fmaf(s_fc[c], w_q_w[c * DD + tid], a);
#pragma unroll 4
        for (int j = 0; j < 32; j++) a = fmaf(s_pe[j], w_q_w[(64 + j) * DD + tid], a);
        out_seed[(size_t)q * DD + tid] = a;
    }
    __syncthreads();

    // phi for learned offsets: per point [sinx4, cosx4, siny4, cosy4]
    for (int i = tid; i < 128; i += DD) {
        int t = i >> 4, j = i & 15;
        float c = (j < 8) ? s_lx[t] : s_ly[t];
        float ang = c * TWO_PI * (float)(1 << (j & 3));
        s_phiL[i] = ((j >> 2) & 1) ? cosf(ang) : sinf(ang);
    }
    __syncthreads();

    float* tb = out_tokens + (size_t)q * 91 * DD + tid;
    const float e1 = e_l1[tid];

    // --- l1 fixed tokens (24): 6x6 patch, shared frac weights ---
    {
        const float xc = x * 0.25f, yc = y * 0.25f;
        const float* m1b = g_m1 + (size_t)b * (H1 * W1) * DD;
        patch_sample<H1, W1, 2>(m1b, xc, yc, tid, [&](int ty, int tx, float v) {
            int idx = ty * 5 + tx;
            if (idx == 12) return;
            int t = (idx < 12) ? idx : idx - 1;
            v += g_phiW[t * DD + tid];
            float g = 0.5f * v * (1.f + erff(v * 0.7071067811865476f));
            tb[t * DD] = g + e1;
        });
    }
    // --- l1 learned tokens (8): arbitrary positions ---
    {
        const float xc = x * 0.25f, yc = y * 0.25f;
        const float wlb = w_loc_b[tid];
        const float* m1b = g_m1 + (size_t)b * (H1 * W1) * DD;
        const float* w2 = s_w2 + tid;
#pragma unroll 2
        for (int t = 0; t < 8; t++) {
            float v = sample_cl(m1b, H1, W1, xc + s_lx[t], yc + s_ly[t], tid);
            const float* ph = s_phiL + t * 16;
#pragma unroll
            for (int j = 0; j < 16; j++) v = fmaf(ph[j], w2[j * DD], v);
            v += wlb;
            float g = 0.5f * v * (1.f + erff(v * 0.7071067811865476f));
            tb[(24 + t) * DD] = g + e1;
        }
    }
    // --- l2 tokens (25): 6x6 patch ---
    {
        const float* m2b = g_m2 + (size_t)b * (H2 * W2) * DD;
        patch_sample<H2, W2, 2>(m2b, x * 0.125f, y * 0.125f, tid, [&](int ty, int tx, float v) {
            int t = ty * 5 + tx;
            tb[(32 + t) * DD] = v + g_add2[t * DD + tid];
        });
    }
    // --- l3 tokens (25): 6x6 patch ---
    {
        const float* m3b = g_m3 + (size_t)b * (H3 * W3) * DD;
        patch_sample<H3, W3, 2>(m3b, x * 0.0625f, y * 0.0625f, tid, [&](int ty, int tx, float v) {
            int t = ty * 5 + tx;
            tb[(57 + t) * DD] = v + g_add3[t * DD + tid];
        });
    }
    // --- l4 tokens (9): 4x4 patch ---
    {
        const float* m4b = g_m4 + (size_t)b * (H4 * W4) * DD;
        patch_sample<H4, W4, 1>(m4b, x * 0.03125f, y * 0.03125f, tid, [&](int ty, int tx, float v) {
            int t = ty * 3 + tx;
            tb[(82 + t) * DD] = v + g_add4[t * DD + tid];
        });
    }
}

// ---------------------------------------------------------------------------
extern "C" void kernel_launch(void* const* d_in, const int* in_sizes, int n_in,
                              void* d_out, int out_size)
{
    const float* feat_l1   = (const float*)d_in[0];
    const float* feat_l2   = (const float*)d_in[1];
    const float* feat_l3   = (const float*)d_in[2];
    const float* feat_l4   = (const float*)d_in[3];
    const float* coords    = (const float*)d_in[4];
    const float* proj_l2_w = (const float*)d_in[5];
    const float* proj_l2_b = (const float*)d_in[6];
    const float* proj_l4_w = (const float*)d_in[7];
    const float* proj_l4_b = (const float*)d_in[8];
    const float* w_off_w   = (const float*)d_in[9];
    const float* w_off_b   = (const float*)d_in[10];
    const float* w_loc_w   = (const float*)d_in[11];
    const float* w_loc_b   = (const float*)d_in[12];
    const float* w_q_w     = (const float*)d_in[13];
    const float* w_q_b     = (const float*)d_in[14];
    const float* e_l1      = (const float*)d_in[15];
    const float* e_l2      = (const float*)d_in[16];
    const float* e_l3      = (const float*)d_in[17];
    const float* e_l4      = (const float*)d_in[18];
    const float* rpe       = (const float*)d_in[19];

    float* out = (float*)d_out;
    float* out_tokens = out;
    float* out_seed = out + (size_t)BB * KK * 91 * DD;

    proj_map_kernel<64, 1><<<dim3(H1 * W1 / 8, BB), DD>>>(feat_l1, w_loc_w, H1 * W1);
    proj_map_kernel<128, 2><<<dim3(H2 * W2 / 8, BB), DD>>>(feat_l2, proj_l2_w, H2 * W2);
    proj_map_kernel<384, 4><<<dim3(H4 * W4 / 8, BB), DD>>>(feat_l4, proj_l4_w, H4 * W4);
    l3_transpose_kernel<<<dim3(H3 * W3 / 32, BB), DD>>>(feat_l3);
    init_tables_kernel<<<83, DD>>>(w_loc_w, w_loc_b, proj_l2_b, e_l2, e_l3,
                                   proj_l4_b, e_l4, rpe);

    token_kernel<<<BB * KK, DD>>>(coords, w_off_w, w_off_b, w_loc_w, w_loc_b,
                                  w_q_w, w_q_b, e_l1, out_tokens, out_seed);
}

// round 3
// speedup vs baseline: 1.4291x; 1.2209x over previous
#include <cuda_runtime.h>
#include <math.h>

#define BB 2
#define KK 4096
#define DD 192
#define H1 96
#define W1 320
#define H2 48
#define W2 160
#define H3 24
#define W3 80
#define H4 12
#define W4 40
#define NQ (BB * KK)
#define QT 8            // queries per block (both kernels)

// Scratch (allocation-free __device__ globals)
__device__ float g_m1[(size_t)BB * H1 * W1 * DD];  // feat_l1 @ w_loc_w[:64]
__device__ float g_c1[(size_t)BB * H1 * W1 * 64];  // feat_l1 channel-last (raw)
__device__ float g_m2[(size_t)BB * H2 * W2 * DD];  // feat_l2 @ proj_l2_w
__device__ float g_m3[(size_t)BB * H3 * W3 * DD];  // feat_l3 channel-last
__device__ float g_m4[(size_t)BB * H4 * W4 * DD];  // feat_l4 @ proj_l4_w
__device__ float g_phiW[24 * DD];                  // phi(fixed_off) @ W2 + w_loc_b
__device__ float g_phiL[(size_t)NQ * 128];         // fourier_pe of learned offsets
__device__ float g_lxy[(size_t)NQ * 16];           // learned offsets: 8x lx then 8x ly

#define TWO_PI 6.283185307179586f

// ---------------------------------------------------------------------------
// Precompute: out[b, p, d] = sum_c feat[b, c, p] * Wm[c, d]   (channel-last)
// ---------------------------------------------------------------------------
template <int CIN, int LVL>
__global__ __launch_bounds__(DD) void proj_map_kernel(
    const float* __restrict__ feat, const float* __restrict__ Wm, int npix)
{
    constexpr int TX = 8;
    __shared__ float sf[CIN * TX];
    float* outmap = (LVL == 1) ? g_m1 : (LVL == 2) ? g_m2 : g_m4;

    const int b = blockIdx.y;
    const int p0 = blockIdx.x * TX;
    const float* fb = feat + (size_t)b * CIN * npix + p0;

    for (int i = threadIdx.x; i < CIN * TX; i += DD) {
        int c = i >> 3, p = i & 7;
        sf[i] = fb[(size_t)c * npix + p];
    }
    __syncthreads();

    if (LVL == 1) {
        for (int i = threadIdx.x; i < 64 * TX; i += DD) {
            int p = i >> 6, c = i & 63;
            g_c1[((size_t)b * npix + p0 + p) * 64 + c] = sf[c * TX + p];
        }
    }

    const int d = threadIdx.x;
    float acc[TX];
#pragma unroll
    for (int p = 0; p < TX; p++) acc[p] = 0.f;

    for (int c = 0; c < CIN; c++) {
        float w = Wm[c * DD + d];
#pragma unroll
        for (int p = 0; p < TX; p++) acc[p] = fmaf(sf[c * TX + p], w, acc[p]);
    }

    float* ob = outmap + ((size_t)b * npix + p0) * DD + d;
#pragma unroll
    for (int p = 0; p < TX; p++) ob[p * DD] = acc[p];
}

// Channel-last transpose for l3
__global__ __launch_bounds__(DD) void l3_transpose_kernel(const float* __restrict__ feat)
{
    __shared__ float s[32][DD + 1];
    const int npix = H3 * W3;
    const int b = blockIdx.y;
    const int p0 = blockIdx.x * 32;

    for (int i = threadIdx.x; i < DD * 32; i += DD) {
        int d = i >> 5, p = i & 31;
        s[p][d] = feat[((size_t)b * DD + d) * npix + p0 + p];
    }
    __syncthreads();

    const int d = threadIdx.x;
#pragma unroll 4
    for (int p = 0; p < 32; p++)
        g_m3[((size_t)b * npix + p0 + p) * DD + d] = s[p][d];
}

// g_phiW = phi(fixed_off) @ w_loc_w[64:80] + w_loc_b
__global__ __launch_bounds__(DD) void init_tables_kernel(
    const float* __restrict__ w_loc_w, const float* __restrict__ w_loc_b)
{
    const int t = blockIdx.x;
    const int d = threadIdx.x;
    int idx = (t < 12) ? t : t + 1;
    float dx = (float)(idx % 5 - 2), dy = (float)(idx / 5 - 2);
    float a = w_loc_b[d];
#pragma unroll
    for (int j = 0; j < 16; j++) {
        float c = (j < 8) ? dx : dy;
        float ang = c * TWO_PI * (float)(1 << (j & 3));
        float v = ((j >> 2) & 1) ? cosf(ang) : sinf(ang);
        a = fmaf(v, w_loc_w[(64 + j) * DD + d], a);
    }
    g_phiW[t * DD + d] = a;
}

// ---------------------------------------------------------------------------
// Seed + learned-offset kernel: QT queries per block, 192 threads.
// w_q_w / w_off_w are streamed once per block (amortized over QT queries).
// ---------------------------------------------------------------------------
__global__ __launch_bounds__(DD) void seed_off_kernel(
    const float* __restrict__ coords,
    const float* __restrict__ w_off_w, const float* __restrict__ w_off_b,
    const float* __restrict__ w_q_w,   const float* __restrict__ w_q_b,
    float* __restrict__ out_seed)
{
    __shared__ float s_f[QT][96];     // [0:64) f_center, [64:96) pe
    __shared__ float s_wo[64 * 16];
    __shared__ float s_lxy[QT][16];   // 8 lx then 8 ly

    const int tid = threadIdx.x;
    const int q0 = blockIdx.x * QT;

    for (int i = tid; i < 64 * 16; i += DD) s_wo[i] = w_off_w[i];

    // f_center: 3 subgroups of 64 threads, each handles queries sub, sub+3, ...
    {
        const int sub = tid >> 6, c = tid & 63;
        for (int q = sub; q < QT; q += 3) {
            const int qi = q0 + q;
            const int b = qi >> 12;
            const float x = coords[2 * qi], y = coords[2 * qi + 1];
            float xs = x * 0.25f, ys = y * 0.25f;
            float x0f = floorf(xs), y0f = floorf(ys);
            float wx1 = xs - x0f, wy1 = ys - y0f;
            float wx0 = 1.f - wx1, wy0 = 1.f - wy1;
            int x0 = (int)x0f, y0 = (int)y0f, x1 = x0 + 1, y1 = y0 + 1;
            bool vx0 = (unsigned)x0 < (unsigned)W1, vx1 = (unsigned)x1 < (unsigned)W1;
            const float* cb = g_c1 + (size_t)b * (H1 * W1) * 64 + c;
            float acc = 0.f;
            if ((unsigned)y0 < (unsigned)H1) {
                if (vx0) acc = fmaf(wx0 * wy0, cb[(size_t)(y0 * W1 + x0) * 64], acc);
                if (vx1) acc = fmaf(wx1 * wy0, cb[(size_t)(y0 * W1 + x1) * 64], acc);
            }
            if ((unsigned)y1 < (unsigned)H1) {
                if (vx0) acc = fmaf(wx0 * wy1, cb[(size_t)(y1 * W1 + x0) * 64], acc);
                if (vx1) acc = fmaf(wx1 * wy1, cb[(size_t)(y1 * W1 + x1) * 64], acc);
            }
            s_f[q][c] = acc;
        }
    }
    // pe_q
    for (int i = tid; i < QT * 32; i += DD) {
        int q = i >> 5, j = i & 31;
        const int qi = q0 + q;
        float cv = (j < 16) ? coords[2 * qi] * (1.f / 1280.f)
                            : coords[2 * qi + 1] * (1.f / 384.f);
        float ang = cv * TWO_PI * (float)(1 << (j & 7));
        s_f[q][64 + j] = ((j >> 3) & 1) ? cosf(ang) : sinf(ang);
    }
    __syncthreads();

    // learned offsets: QT*16 = 128 outputs
    if (tid < QT * 16) {
        int q = tid >> 4, j = tid & 15;
        float a = w_off_b[j];
#pragma unroll 8
        for (int c = 0; c < 64; c++) a = fmaf(s_f[q][c], s_wo[c * 16 + j], a);
        float v = 6.f * tanhf(a);
        int slot = (j & 1) ? 8 + (j >> 1) : (j >> 1);
        s_lxy[q][slot] = v;
        g_lxy[(size_t)(q0 + q) * 16 + slot] = v;
    }
    __syncthreads();

    // phi of learned offsets -> g_phiL
    for (int i = tid; i < QT * 128; i += DD) {
        int q = i >> 7, r = i & 127;
        int t = r >> 4, j = r & 15;
        float c = (j < 8) ? s_lxy[q][t] : s_lxy[q][8 + t];
        float ang = c * TWO_PI * (float)(1 << (j & 3));
        g_phiL[(size_t)(q0 + q) * 128 + r] = ((j >> 2) & 1) ? cosf(ang) : sinf(ang);
    }

    // seed = [f_center, pe] @ w_q_w + w_q_b ; w_q_w streamed once per block
    {
        const int d = tid;
        float acc[QT];
        float bq = w_q_b[d];
#pragma unroll
        for (int q = 0; q < QT; q++) acc[q] = bq;
        for (int c = 0; c < 96; c++) {
            float w = w_q_w[c * DD + d];
#pragma unroll
            for (int q = 0; q < QT; q++) acc[q] = fmaf(s_f[q][c], w, acc[q]);
        }
#pragma unroll
        for (int q = 0; q < QT; q++)
            out_seed[(size_t)(q0 + q) * DD + d] = acc[q];
    }
}

// ---------------------------------------------------------------------------
// Bilinear sample from a channel-last map (arbitrary position)
// ---------------------------------------------------------------------------
__device__ __forceinline__ float sample_cl(const float* __restrict__ mb, int H, int W,
                                           float x, float y, int d)
{
    float x0f = floorf(x), y0f = floorf(y);
    float wx1 = x - x0f, wy1 = y - y0f;
    float wx0 = 1.f - wx1, wy0 = 1.f - wy1;
    int x0 = (int)x0f, y0 = (int)y0f;
    int x1 = x0 + 1, y1 = y0 + 1;
    bool vx0 = (unsigned)x0 < (unsigned)W;
    bool vx1 = (unsigned)x1 < (unsigned)W;

    float acc = 0.f;
    if ((unsigned)y0 < (unsigned)H) {
        const float* r = mb + (size_t)(y0 * W) * DD + d;
        if (vx0) acc = fmaf(wx0 * wy0, r[(size_t)x0 * DD], acc);
        if (vx1) acc = fmaf(wx1 * wy0, r[(size_t)x1 * DD], acc);
    }
    if ((unsigned)y1 < (unsigned)H) {
        const float* r = mb + (size_t)(y1 * W) * DD + d;
        if (vx0) acc = fmaf(wx0 * wy1, r[(size_t)x0 * DD], acc);
        if (vx1) acc = fmaf(wx1 * wy1, r[(size_t)x1 * DD], acc);
    }
    return acc;
}

// Patch-shared bilinear sampling for an integer-offset grid (separable interp).
template <int H, int W, int R, typename F>
__device__ __forceinline__ void patch_sample(const float* __restrict__ mb,
                                             float xs, float ys, int d, F&& emit)
{
    constexpr int PC = 2 * R + 2;
    float xf = floorf(xs), yf = floorf(ys);
    float wx1 = xs - xf, wx0 = 1.f - wx1;
    float wy1 = ys - yf, wy0 = 1.f - wy1;
    int bx0 = (int)xf - R, by0 = (int)yf - R;

    const float* md = mb + d;
    float hprev[PC - 1];

    for (int r = 0; r < PC; r++) {
        int yy = by0 + r;
        bool yok = (unsigned)yy < (unsigned)H;
        float p[PC];
#pragma unroll
        for (int c = 0; c < PC; c++) {
            int xx = bx0 + c;
            bool ok = yok && ((unsigned)xx < (unsigned)W);
            p[c] = ok ? md[(size_t)(yy * W + xx) * DD] : 0.f;
        }
        float hcur[PC - 1];
#pragma unroll
        for (int c = 0; c < PC - 1; c++) hcur[c] = fmaf(wx1, p[c + 1], wx0 * p[c]);
        if (r > 0) {
#pragma unroll
            for (int c = 0; c < PC - 1; c++)
                emit(r - 1, c, fmaf(wy1, hcur[c], wy0 * hprev[c]));
        }
#pragma unroll
        for (int c = 0; c < PC - 1; c++) hprev[c] = hcur[c];
    }
}

// ---------------------------------------------------------------------------
// Gather kernel: QT queries per block; tables staged in smem once per block.
// Dynamic smem layout: rpe[25*192] | phiW[24*192] | w2[16*192] | phiL[128] | lxy[16]
// ---------------------------------------------------------------------------
__global__ __launch_bounds__(DD) void gather_kernel(
    const float* __restrict__ coords,
    const float* __restrict__ w_loc_w, const float* __restrict__ w_loc_b,
    const float* __restrict__ proj_l2_b, const float* __restrict__ proj_l4_b,
    const float* __restrict__ e_l1, const float* __restrict__ e_l2,
    const float* __restrict__ e_l3, const float* __restrict__ e_l4,
    const float* __restrict__ rpe,
    float* __restrict__ out_tokens)
{
    extern __shared__ float sm[];
    float* s_rpe  = sm;                 // 4800
    float* s_phiW = s_rpe + 25 * DD;    // 4608
    float* s_w2   = s_phiW + 24 * DD;   // 3072
    float* s_phiL = s_w2 + 16 * DD;     // 128
    float* s_lxy  = s_phiL + 128;       // 16

    const int tid = threadIdx.x;
    const int q0 = blockIdx.x * QT;
    const int d = tid;

    for (int i = tid; i < 25 * DD; i += DD) s_rpe[i]  = rpe[i];
    for (int i = tid; i < 24 * DD; i += DD) s_phiW[i] = g_phiW[i];
    for (int i = tid; i < 16 * DD; i += DD) s_w2[i]   = w_loc_w[64 * DD + i];

    const float e1  = e_l1[d];
    const float wlb = w_loc_b[d];
    const float b2e = proj_l2_b[d] + e_l2[d];
    const float e3  = e_l3[d];
    const float b4e = proj_l4_b[d] + e_l4[d];

    for (int q = 0; q < QT; q++) {
        const int qi = q0 + q;
        const int b = qi >> 12;
        __syncthreads();                 // previous iter consumers done
        if (tid < 128) s_phiL[tid] = g_phiL[(size_t)qi * 128 + tid];
        else if (tid < 144) s_lxy[tid - 128] = g_lxy[(size_t)qi * 16 + (tid - 128)];
        __syncthreads();

        const float x = coords[2 * qi], y = coords[2 * qi + 1];
        float* tb = out_tokens + (size_t)qi * 91 * DD + d;

        // --- l1 fixed tokens (24): 6x6 shared patch ---
        {
            const float* m1b = g_m1 + (size_t)b * (H1 * W1) * DD;
            patch_sample<H1, W1, 2>(m1b, x * 0.25f, y * 0.25f, d,
                [&](int ty, int tx, float v) {
                    int idx = ty * 5 + tx;
                    if (idx == 12) return;
                    int t = (idx < 12) ? idx : idx - 1;
                    v += s_phiW[t * DD + d];
                    float g = 0.5f * v * (1.f + erff(v * 0.7071067811865476f));
                    tb[t * DD] = g + e1;
                });
        }
        // --- l1 learned tokens (8) ---
        {
            const float xc = x * 0.25f, yc = y * 0.25f;
            const float* m1b = g_m1 + (size_t)b * (H1 * W1) * DD;
            const float* w2 = s_w2 + d;
#pragma unroll 2
            for (int t = 0; t < 8; t++) {
                float v = sample_cl(m1b, H1, W1, xc + s_lxy[t], yc + s_lxy[8 + t], d);
                const float* ph = s_phiL + t * 16;
#pragma unroll
                for (int j = 0; j < 16; j++) v = fmaf(ph[j], w2[j * DD], v);
                v += wlb;
                float g = 0.5f * v * (1.f + erff(v * 0.7071067811865476f));
                tb[(24 + t) * DD] = g + e1;
            }
        }
        // --- l2 tokens (25) ---
        {
            const float* m2b = g_m2 + (size_t)b * (H2 * W2) * DD;
            patch_sample<H2, W2, 2>(m2b, x * 0.125f, y * 0.125f, d,
                [&](int ty, int tx, float v) {
                    int t = ty * 5 + tx;
                    tb[(32 + t) * DD] = v + b2e + s_rpe[t * DD + d];
                });
        }
        // --- l3 tokens (25) ---
        {
            const float* m3b = g_m3 + (size_t)b * (H3 * W3) * DD;
            patch_sample<H3, W3, 2>(m3b, x * 0.0625f, y * 0.0625f, d,
                [&](int ty, int tx, float v) {
                    int t = ty * 5 + tx;
                    tb[(57 + t) * DD] = v + e3 + s_rpe[t * DD + d];
                });
        }
        // --- l4 tokens (9) ---
        {
            const float* m4b = g_m4 + (size_t)b * (H4 * W4) * DD;
            patch_sample<H4, W4, 1>(m4b, x * 0.03125f, y * 0.03125f, d,
                [&](int ty, int tx, float v) {
                    int t = ty * 3 + tx;
                    int ridx = 6 + (t / 3) * 5 + (t % 3);
                    tb[(82 + t) * DD] = v + b4e + s_rpe[ridx * DD + d];
                });
        }
    }
}

// ---------------------------------------------------------------------------
extern "C" void kernel_launch(void* const* d_in, const int* in_sizes, int n_in,
                              void* d_out, int out_size)
{
    const float* feat_l1   = (const float*)d_in[0];
    const float* feat_l2   = (const float*)d_in[1];
    const float* feat_l3   = (const float*)d_in[2];
    const float* feat_l4   = (const float*)d_in[3];
    const float* coords    = (const float*)d_in[4];
    const float* proj_l2_w = (const float*)d_in[5];
    const float* proj_l2_b = (const float*)d_in[6];
    const float* proj_l4_w = (const float*)d_in[7];
    const float* proj_l4_b = (const float*)d_in[8];
    const float* w_off_w   = (const float*)d_in[9];
    const float* w_off_b   = (const float*)d_in[10];
    const float* w_loc_w   = (const float*)d_in[11];
    const float* w_loc_b   = (const float*)d_in[12];
    const float* w_q_w     = (const float*)d_in[13];
    const float* w_q_b     = (const float*)d_in[14];
    const float* e_l1      = (const float*)d_in[15];
    const float* e_l2      = (const float*)d_in[16];
    const float* e_l3      = (const float*)d_in[17];
    const float* e_l4      = (const float*)d_in[18];
    const float* rpe       = (const float*)d_in[19];

    float* out = (float*)d_out;
    float* out_tokens = out;
    float* out_seed = out + (size_t)NQ * 91 * DD;

    static int smem_set = 0;
    const int gather_smem = (25 * DD + 24 * DD + 16 * DD + 128 + 16) * 4;
    if (!smem_set) {
        cudaFuncSetAttribute(gather_kernel,
                             cudaFuncAttributeMaxDynamicSharedMemorySize, gather_smem);
        smem_set = 1;
    }

    proj_map_kernel<64, 1><<<dim3(H1 * W1 / 8, BB), DD>>>(feat_l1, w_loc_w, H1 * W1);
    proj_map_kernel<128, 2><<<dim3(H2 * W2 / 8, BB), DD>>>(feat_l2, proj_l2_w, H2 * W2);
    proj_map_kernel<384, 4><<<dim3(H4 * W4 / 8, BB), DD>>>(feat_l4, proj_l4_w, H4 * W4);
    l3_transpose_kernel<<<dim3(H3 * W3 / 32, BB), DD>>>(feat_l3);
    init_tables_kernel<<<24, DD>>>(w_loc_w, w_loc_b);

    seed_off_kernel<<<NQ / QT, DD>>>(coords, w_off_w, w_off_b, w_q_w, w_q_b, out_seed);

    gather_kernel<<<NQ / QT, DD, gather_smem>>>(coords, w_loc_w, w_loc_b,
                                                proj_l2_b, proj_l4_b,
                                                e_l1, e_l2, e_l3, e_l4, rpe,
                                                out_tokens);
}

// round 4
// speedup vs baseline: 1.7003x; 1.1898x over previous
#include <cuda_runtime.h>
#include <math.h>

#define BB 2
#define KK 4096
#define DD 192
#define D2 96            // float2 channels
#define H1 96
#define W1 320
#define H2 48
#define W2 160
#define H3 24
#define W3 80
#define H4 12
#define W4 40
#define NQ (BB * KK)
#define QT 8

// Scratch (allocation-free __device__ globals, 16B aligned for vector access)
__device__ __align__(16) float g_m1[(size_t)BB * H1 * W1 * DD];
__device__ __align__(16) float g_c1[(size_t)BB * H1 * W1 * 64];
__device__ __align__(16) float g_m2[(size_t)BB * H2 * W2 * DD];
__device__ __align__(16) float g_m3[(size_t)BB * H3 * W3 * DD];
__device__ __align__(16) float g_m4[(size_t)BB * H4 * W4 * DD];
__device__ __align__(16) float g_phiW[24 * DD];               // phi(fixed)@W2 + w_loc_b
__device__ __align__(16) float g_phiLW2[(size_t)NQ * 8 * DD]; // phi(learned)@W2 + w_loc_b
__device__ __align__(16) float g_lxy[(size_t)NQ * 16];        // interleaved (lx,ly) pairs

#define TWO_PI 6.283185307179586f

// ---------------- packed f32x2 helpers ----------------
__device__ __forceinline__ unsigned long long pk(float2 v) {
    unsigned long long r;
    asm("mov.b64 %0, {%1, %2};" : "=l"(r) : "f"(v.x), "f"(v.y));
    return r;
}
__device__ __forceinline__ float2 upk(unsigned long long r) {
    float2 v;
    asm("mov.b64 {%0, %1}, %2;" : "=f"(v.x), "=f"(v.y) : "l"(r));
    return v;
}
__device__ __forceinline__ float2 f2fma(float2 a, float2 b, float2 c) {
    unsigned long long d;
    asm("fma.rn.f32x2 %0, %1, %2, %3;" : "=l"(d) : "l"(pk(a)), "l"(pk(b)), "l"(pk(c)));
    return upk(d);
}
__device__ __forceinline__ float2 f2mul(float2 a, float2 b) {
    unsigned long long d;
    asm("mul.rn.f32x2 %0, %1, %2;" : "=l"(d) : "l"(pk(a)), "l"(pk(b)));
    return upk(d);
}
__device__ __forceinline__ float2 f2add(float2 a, float2 b) {
    unsigned long long d;
    asm("add.rn.f32x2 %0, %1, %2;" : "=l"(d) : "l"(pk(a)), "l"(pk(b)));
    return upk(d);
}
__device__ __forceinline__ float2 bc2(float s) { return make_float2(s, s); }

__device__ __forceinline__ float gelu1(float v) {
    return 0.5f * v * (1.f + erff(v * 0.7071067811865476f));
}
__device__ __forceinline__ float2 gelu2(float2 v) {
    return make_float2(gelu1(v.x), gelu1(v.y));
}

// ---------------------------------------------------------------------------
// Precompute: out[b, p, d] = sum_c feat[b, c, p] * Wm[c, d]   (channel-last)
// ---------------------------------------------------------------------------
template <int CIN, int LVL>
__global__ __launch_bounds__(DD) void proj_map_kernel(
    const float* __restrict__ feat, const float* __restrict__ Wm, int npix)
{
    constexpr int TX = 8;
    __shared__ float sf[CIN * TX];
    float* outmap = (LVL == 1) ? g_m1 : (LVL == 2) ? g_m2 : g_m4;

    const int b = blockIdx.y;
    const int p0 = blockIdx.x * TX;
    const float* fb = feat + (size_t)b * CIN * npix + p0;

    for (int i = threadIdx.x; i < CIN * TX; i += DD) {
        int c = i >> 3, p = i & 7;
        sf[i] = fb[(size_t)c * npix + p];
    }
    __syncthreads();

    if (LVL == 1) {
        for (int i = threadIdx.x; i < 64 * TX; i += DD) {
            int p = i >> 6, c = i & 63;
            g_c1[((size_t)b * npix + p0 + p) * 64 + c] = sf[c * TX + p];
        }
    }

    const int d = threadIdx.x;
    float acc[TX];
#pragma unroll
    for (int p = 0; p < TX; p++) acc[p] = 0.f;

    for (int c = 0; c < CIN; c++) {
        float w = Wm[c * DD + d];
#pragma unroll
        for (int p = 0; p < TX; p++) acc[p] = fmaf(sf[c * TX + p], w, acc[p]);
    }

    float* ob = outmap + ((size_t)b * npix + p0) * DD + d;
#pragma unroll
    for (int p = 0; p < TX; p++) ob[p * DD] = acc[p];
}

// Channel-last transpose for l3 (z-split over channel chunks of 32)
__global__ __launch_bounds__(256) void l3_transpose_kernel(const float* __restrict__ feat)
{
    __shared__ float s[32][33];
    const int npix = H3 * W3;
    const int b = blockIdx.y;
    const int p0 = blockIdx.x * 32;
    const int d0 = blockIdx.z * 32;

#pragma unroll
    for (int k = 0; k < 4; k++) {
        int i = threadIdx.x + k * 256;
        int d = i >> 5, p = i & 31;
        s[p][d] = feat[((size_t)b * DD + d0 + d) * npix + p0 + p];
    }
    __syncthreads();
#pragma unroll
    for (int k = 0; k < 4; k++) {
        int i = threadIdx.x + k * 256;
        int p = i >> 5, d = i & 31;
        g_m3[((size_t)b * npix + p0 + p) * DD + d0 + d] = s[p][d];
    }
}

// g_phiW = phi(fixed_off) @ w_loc_w[64:80] + w_loc_b
__global__ __launch_bounds__(DD) void init_tables_kernel(
    const float* __restrict__ w_loc_w, const float* __restrict__ w_loc_b)
{
    const int t = blockIdx.x;
    const int d = threadIdx.x;
    int idx = (t < 12) ? t : t + 1;
    float dx = (float)(idx % 5 - 2), dy = (float)(idx / 5 - 2);
    float a = w_loc_b[d];
#pragma unroll
    for (int j = 0; j < 16; j++) {
        float c = (j < 8) ? dx : dy;
        float ang = c * TWO_PI * (float)(1 << (j & 3));
        float v = ((j >> 2) & 1) ? cosf(ang) : sinf(ang);
        a = fmaf(v, w_loc_w[(64 + j) * DD + d], a);
    }
    g_phiW[t * DD + d] = a;
}

// ---------------------------------------------------------------------------
// Seed + learned-offset kernel: QT queries per block, 192 threads.
// Also emits g_phiLW2 = phi(learned)@W2 + w_loc_b and g_lxy pairs.
// ---------------------------------------------------------------------------
__global__ __launch_bounds__(DD) void seed_off_kernel(
    const float* __restrict__ coords,
    const float* __restrict__ w_off_w, const float* __restrict__ w_off_b,
    const float* __restrict__ w_loc_w, const float* __restrict__ w_loc_b,
    const float* __restrict__ w_q_w,   const float* __restrict__ w_q_b,
    float* __restrict__ out_seed)
{
    __shared__ float s_f[QT][96];     // [0:64) f_center, [64:96) pe
    __shared__ float s_wo[64 * 16];
    __shared__ float s_w2[16 * DD];
    __shared__ float s_lxy[QT][16];   // 8 lx then 8 ly
    __shared__ float s_phi[QT * 128];

    const int tid = threadIdx.x;
    const int q0 = blockIdx.x * QT;

    for (int i = tid; i < 64 * 16; i += DD) s_wo[i] = w_off_w[i];
    for (int i = tid; i < 16 * DD; i += DD) s_w2[i] = w_loc_w[64 * DD + i];

    // f_center: 3 subgroups of 64 threads
    {
        const int sub = tid >> 6, c = tid & 63;
        for (int q = sub; q < QT; q += 3) {
            const int qi = q0 + q;
            const int b = qi >> 12;
            const float x = coords[2 * qi], y = coords[2 * qi + 1];
            float xs = x * 0.25f, ys = y * 0.25f;
            float x0f = floorf(xs), y0f = floorf(ys);
            float wx1 = xs - x0f, wy1 = ys - y0f;
            float wx0 = 1.f - wx1, wy0 = 1.f - wy1;
            int x0 = (int)x0f, y0 = (int)y0f, x1 = x0 + 1, y1 = y0 + 1;
            bool vx0 = (unsigned)x0 < (unsigned)W1, vx1 = (unsigned)x1 < (unsigned)W1;
            const float* cb = g_c1 + (size_t)b * (H1 * W1) * 64 + c;
            float acc = 0.f;
            if ((unsigned)y0 < (unsigned)H1) {
                if (vx0) acc = fmaf(wx0 * wy0, cb[(size_t)(y0 * W1 + x0) * 64], acc);
                if (vx1) acc = fmaf(wx1 * wy0, cb[(size_t)(y0 * W1 + x1) * 64], acc);
            }
            if ((unsigned)y1 < (unsigned)H1) {
                if (vx0) acc = fmaf(wx0 * wy1, cb[(size_t)(y1 * W1 + x0) * 64], acc);
                if (vx1) acc = fmaf(wx1 * wy1, cb[(size_t)(y1 * W1 + x1) * 64], acc);
            }
            s_f[q][c] = acc;
        }
    }
    // pe_q
    for (int i = tid; i < QT * 32; i += DD) {
        int q = i >> 5, j = i & 31;
        const int qi = q0 + q;
        float cv = (j < 16) ? coords[2 * qi] * (1.f / 1280.f)
                            : coords[2 * qi + 1] * (1.f / 384.f);
        float ang = cv * TWO_PI * (float)(1 << (j & 7));
        s_f[q][64 + j] = ((j >> 3) & 1) ? cosf(ang) : sinf(ang);
    }
    __syncthreads();

    // learned offsets
    if (tid < QT * 16) {
        int q = tid >> 4, j = tid & 15;
        float a = w_off_b[j];
#pragma unroll 8
        for (int c = 0; c < 64; c++) a = fmaf(s_f[q][c], s_wo[c * 16 + j], a);
        float v = 6.f * tanhf(a);
        int slot = (j & 1) ? 8 + (j >> 1) : (j >> 1);
        s_lxy[q][slot] = v;
        g_lxy[(size_t)(q0 + q) * 16 + (j >> 1) * 2 + (j & 1)] = v;  // (lx,ly) pairs
    }
    __syncthreads();

    // phi of learned offsets
    for (int i = tid; i < QT * 128; i += DD) {
        int q = i >> 7, r = i & 127;
        int t = r >> 4, j = r & 15;
        float c = (j < 8) ? s_lxy[q][t] : s_lxy[q][8 + t];
        float ang = c * TWO_PI * (float)(1 << (j & 3));
        s_phi[i] = ((j >> 2) & 1) ? cosf(ang) : sinf(ang);
    }

    // seed = [f_center, pe] @ w_q_w + w_q_b
    {
        const int d = tid;
        float acc[QT];
        float bq = w_q_b[d];
#pragma unroll
        for (int q = 0; q < QT; q++) acc[q] = bq;
        for (int c = 0; c < 96; c++) {
            float w = w_q_w[c * DD + d];
#pragma unroll
            for (int q = 0; q < QT; q++) acc[q] = fmaf(s_f[q][c], w, acc[q]);
        }
#pragma unroll
        for (int q = 0; q < QT; q++)
            out_seed[(size_t)(q0 + q) * DD + d] = acc[q];
    }
    __syncthreads();

    // g_phiLW2[qi, t, d] = phi[q][t] @ w2 + w_loc_b
    {
        const int d = tid;
        const float wlbd = w_loc_b[d];
        for (int qt = 0; qt < QT * 8; qt++) {
            int q = qt >> 3, t = qt & 7;
            float a = wlbd;
            const float* ph = &s_phi[q * 128 + t * 16];
#pragma unroll
            for (int j = 0; j < 16; j++) a = fmaf(ph[j], s_w2[j * DD + d], a);
            g_phiLW2[((size_t)(q0 + q) * 8 + t) * DD + d] = a;
        }
    }
}

// ---------------------------------------------------------------------------
// float2 bilinear sample (arbitrary position); md pre-offset by channel
// ---------------------------------------------------------------------------
template <int H, int W>
__device__ __forceinline__ float2 sample2(const float2* __restrict__ md,
                                          float x, float y)
{
    float x0f = floorf(x), y0f = floorf(y);
    float wx1 = x - x0f, wy1 = y - y0f;
    float wx0 = 1.f - wx1, wy0 = 1.f - wy1;
    int x0 = (int)x0f, y0 = (int)y0f;
    int x1 = x0 + 1, y1 = y0 + 1;
    bool vx0 = (unsigned)x0 < (unsigned)W;
    bool vx1 = (unsigned)x1 < (unsigned)W;
    bool vy0 = (unsigned)y0 < (unsigned)H;
    bool vy1 = (unsigned)y1 < (unsigned)H;

    float2 z = make_float2(0.f, 0.f);
    float2 p00 = (vy0 && vx0) ? md[(size_t)(y0 * W + x0) * D2] : z;
    float2 p01 = (vy0 && vx1) ? md[(size_t)(y0 * W + x1) * D2] : z;
    float2 p10 = (vy1 && vx0) ? md[(size_t)(y1 * W + x0) * D2] : z;
    float2 p11 = (vy1 && vx1) ? md[(size_t)(y1 * W + x1) * D2] : z;

    float2 h0 = f2fma(bc2(wx1), p01, f2mul(bc2(wx0), p00));
    float2 h1 = f2fma(bc2(wx1), p11, f2mul(bc2(wx0), p10));
    return f2fma(bc2(wy1), h1, f2mul(bc2(wy0), h0));
}

// Patch-shared float2 bilinear for integer-offset grids (separable interp)
template <int H, int W, int R, typename F>
__device__ __forceinline__ void patch_sample2(const float2* __restrict__ md,
                                              float xs, float ys, F&& emit)
{
    constexpr int PC = 2 * R + 2;
    float xf = floorf(xs), yf = floorf(ys);
    float2 bwx1 = bc2(xs - xf), bwx0 = bc2(1.f - (xs - xf));
    float2 bwy1 = bc2(ys - yf), bwy0 = bc2(1.f - (ys - yf));
    int bx0 = (int)xf - R, by0 = (int)yf - R;

    float2 hprev[PC - 1];
    const float2 z = make_float2(0.f, 0.f);

    for (int r = 0; r < PC; r++) {
        int yy = by0 + r;
        bool yok = (unsigned)yy < (unsigned)H;
        float2 p[PC];
#pragma unroll
        for (int c = 0; c < PC; c++) {
            int xx = bx0 + c;
            bool ok = yok && ((unsigned)xx < (unsigned)W);
            p[c] = ok ? md[(size_t)(yy * W + xx) * D2] : z;
        }
        float2 hcur[PC - 1];
#pragma unroll
        for (int c = 0; c < PC - 1; c++)
            hcur[c] = f2fma(bwx1, p[c + 1], f2mul(bwx0, p[c]));
        if (r > 0) {
#pragma unroll
            for (int c = 0; c < PC - 1; c++)
                emit(r - 1, c, f2fma(bwy1, hcur[c], f2mul(bwy0, hprev[c])));
        }
#pragma unroll
        for (int c = 0; c < PC - 1; c++) hprev[c] = hcur[c];
    }
}

// ---------------------------------------------------------------------------
// Gather kernel: 192 threads = 2 independent 96-thread query groups.
// Group g handles queries q0+g, q0+g+2, ... (no syncs after table load).
// ---------------------------------------------------------------------------
__global__ __launch_bounds__(DD) void gather_kernel(
    const float* __restrict__ coords,
    const float* __restrict__ proj_l2_b, const float* __restrict__ proj_l4_b,
    const float* __restrict__ e_l1, const float* __restrict__ e_l2,
    const float* __restrict__ e_l3, const float* __restrict__ e_l4,
    const float* __restrict__ rpe,
    float* __restrict__ out_tokens)
{
    __shared__ float2 s_rpe[25 * D2];
    __shared__ float2 s_phiW[24 * D2];

    const int tid = threadIdx.x;
    const int q0 = blockIdx.x * QT;
    const int g = tid / D2;
    const int c = tid % D2;

    {
        const float2* rp = (const float2*)rpe;
        const float2* pw = (const float2*)g_phiW;
        for (int i = tid; i < 25 * D2; i += DD) s_rpe[i] = rp[i];
        for (int i = tid; i < 24 * D2; i += DD) s_phiW[i] = pw[i];
    }
    __syncthreads();

    const float2 e1  = ((const float2*)e_l1)[c];
    const float2 b2e = f2add(((const float2*)proj_l2_b)[c], ((const float2*)e_l2)[c]);
    const float2 e3  = ((const float2*)e_l3)[c];
    const float2 b4e = f2add(((const float2*)proj_l4_b)[c], ((const float2*)e_l4)[c]);

    const float2* crd = (const float2*)coords;
    const float2* lxy2 = (const float2*)g_lxy;
    const float2* phiLW2 = (const float2*)g_phiLW2;

    for (int qq = g; qq < QT; qq += 2) {
        const int qi = q0 + qq;
        const int b = qi >> 12;
        const float2 xy = __ldg(&crd[qi]);
        const float x = xy.x, y = xy.y;
        float2* tb = (float2*)out_tokens + (size_t)qi * 91 * D2 + c;

        // --- l1 fixed tokens (24): 6x6 shared patch ---
        {
            const float2* m1b = (const float2*)g_m1 + (size_t)b * (H1 * W1) * D2 + c;
            patch_sample2<H1, W1, 2>(m1b, x * 0.25f, y * 0.25f,
                [&](int ty, int tx, float2 v) {
                    int idx = ty * 5 + tx;
                    if (idx == 12) return;
                    int t = (idx < 12) ? idx : idx - 1;
                    v = f2add(v, s_phiW[t * D2 + c]);
                    tb[t * D2] = f2add(gelu2(v), e1);
                });
        }
        // --- l1 learned tokens (8) ---
        {
            const float xc = x * 0.25f, yc = y * 0.25f;
            const float2* m1b = (const float2*)g_m1 + (size_t)b * (H1 * W1) * D2 + c;
#pragma unroll 2
            for (int t = 0; t < 8; t++) {
                float2 off = __ldg(&lxy2[(size_t)qi * 8 + t]);
                float2 v = sample2<H1, W1>(m1b, xc + off.x, yc + off.y);
                float2 pw = __ldg(&phiLW2[((size_t)qi * 8 + t) * D2 + c]);
                v = f2add(v, pw);
                tb[(24 + t) * D2] = f2add(gelu2(v), e1);
            }
        }
        // --- l2 tokens (25) ---
        {
            const float2* m2b = (const float2*)g_m2 + (size_t)b * (H2 * W2) * D2 + c;
            patch_sample2<H2, W2, 2>(m2b, x * 0.125f, y * 0.125f,
                [&](int ty, int tx, float2 v) {
                    int t = ty * 5 + tx;
                    tb[(32 + t) * D2] = f2add(f2add(v, b2e), s_rpe[t * D2 + c]);
                });
        }
        // --- l3 tokens (25) ---
        {
            const float2* m3b = (const float2*)g_m3 + (size_t)b * (H3 * W3) * D2 + c;
            patch_sample2<H3, W3, 2>(m3b, x * 0.0625f, y * 0.0625f,
                [&](int ty, int tx, float2 v) {
                    int t = ty * 5 + tx;
                    tb[(57 + t) * D2] = f2add(f2add(v, e3), s_rpe[t * D2 + c]);
                });
        }
        // --- l4 tokens (9) ---
        {
            const float2* m4b = (const float2*)g_m4 + (size_t)b * (H4 * W4) * D2 + c;
            patch_sample2<H4, W4, 1>(m4b, x * 0.03125f, y * 0.03125f,
                [&](int ty, int tx, float2 v) {
                    int t = ty * 3 + tx;
                    int ridx = 6 + (t / 3) * 5 + (t % 3);
                    tb[(82 + t) * D2] = f2add(f2add(v, b4e), s_rpe[ridx * D2 + c]);
                });
        }
    }
}

// ---------------------------------------------------------------------------
extern "C" void kernel_launch(void* const* d_in, const int* in_sizes, int n_in,
                              void* d_out, int out_size)
{
    const float* feat_l1   = (const float*)d_in[0];
    const float* feat_l2   = (const float*)d_in[1];
    const float* feat_l3   = (const float*)d_in[2];
    const float* feat_l4   = (const float*)d_in[3];
    const float* coords    = (const float*)d_in[4];
    const float* proj_l2_w = (const float*)d_in[5];
    const float* proj_l2_b = (const float*)d_in[6];
    const float* proj_l4_w = (const float*)d_in[7];
    const float* proj_l4_b = (const float*)d_in[8];
    const float* w_off_w   = (const float*)d_in[9];
    const float* w_off_b   = (const float*)d_in[10];
    const float* w_loc_w   = (const float*)d_in[11];
    const float* w_loc_b   = (const float*)d_in[12];
    const float* w_q_w     = (const float*)d_in[13];
    const float* w_q_b     = (const float*)d_in[14];
    const float* e_l1      = (const float*)d_in[15];
    const float* e_l2      = (const float*)d_in[16];
    const float* e_l3      = (const float*)d_in[17];
    const float* e_l4      = (const float*)d_in[18];
    const float* rpe       = (const float*)d_in[19];

    float* out = (float*)d_out;
    float* out_tokens = out;
    float* out_seed = out + (size_t)NQ * 91 * DD;

    proj_map_kernel<64, 1><<<dim3(H1 * W1 / 8, BB), DD>>>(feat_l1, w_loc_w, H1 * W1);
    proj_map_kernel<128, 2><<<dim3(H2 * W2 / 8, BB), DD>>>(feat_l2, proj_l2_w, H2 * W2);
    proj_map_kernel<384, 4><<<dim3(H4 * W4 / 8, BB), DD>>>(feat_l4, proj_l4_w, H4 * W4);
    l3_transpose_kernel<<<dim3(H3 * W3 / 32, BB, 6), 256>>>(feat_l3);
    init_tables_kernel<<<24, DD>>>(w_loc_w, w_loc_b);

    seed_off_kernel<<<NQ / QT, DD>>>(coords, w_off_w, w_off_b, w_loc_w, w_loc_b,
                                     w_q_w, w_q_b, out_seed);

    gather_kernel<<<NQ / QT, DD>>>(coords, proj_l2_b, proj_l4_b,
                                   e_l1, e_l2, e_l3, e_l4, rpe, out_tokens);
}